// round 1
// baseline (speedup 1.0000x reference)
#include <cuda_runtime.h>
#include <math_constants.h>

// Problem constants
#define B_ 8
#define T_ 8192
#define L_ 256
#define D_ 512
#define H_ 8
// HD = 64, scale = 1/8

// ---------------- scratch (device globals; no allocs allowed) ----------------
__device__ float g_kv [(size_t)B_ * T_ * 2 * D_];  // [B*T, 1024]  (k | v interleaved per row)
__device__ float g_q  [(size_t)B_ * L_ * D_];      // [B*L, 512]
__device__ float g_att[(size_t)B_ * L_ * D_];      // [B*L, 512]

// ---------------- f32x2 helpers (FFMA2 — only reachable via PTX) ----------------
__device__ __forceinline__ unsigned long long pk2(float x) {
    unsigned long long r;
    asm("mov.b64 %0, {%1, %1};" : "=l"(r) : "f"(x));
    return r;
}
__device__ __forceinline__ void fma2(unsigned long long &d, unsigned long long a,
                                     unsigned long long b) {
    asm("fma.rn.f32x2 %0, %1, %2, %0;" : "+l"(d) : "l"(a), "l"(b));
}

// =============================================================================
// SGEMM with bias: C[M,N] = A[M,K] @ B[K,N] + bias[N]   (all row-major fp32)
// 128x128 tile, Kt=16, 256 threads, 8x8 microtile, f32x2 accumulation.
// =============================================================================
__global__ __launch_bounds__(256)
void sgemm_bias(const float* __restrict__ A, const float* __restrict__ Bm,
                const float* __restrict__ bias, float* __restrict__ C,
                int M, int N, int K)
{
    __shared__ float As[16][128];   // transposed A tile: As[k][m]
    __shared__ float Bs[16][128];   // Bs[k][n]

    const int tid = threadIdx.x;
    const int tx = tid & 15, ty = tid >> 4;
    const int bm = blockIdx.y * 128;
    const int bn = blockIdx.x * 128;

    unsigned long long acc[8][4];
    #pragma unroll
    for (int i = 0; i < 8; i++)
        #pragma unroll
        for (int j = 0; j < 4; j++) acc[i][j] = 0ull;

    for (int k0 = 0; k0 < K; k0 += 16) {
        #pragma unroll
        for (int q = 0; q < 2; q++) {
            int idx = tid * 2 + q;
            // A tile: 128 rows x 16 k = 512 float4  (m = idx>>2, k4 = idx&3)
            int m = idx >> 2, kk4 = (idx & 3) << 2;
            float4 fa = *reinterpret_cast<const float4*>(
                A + (size_t)(bm + m) * K + k0 + kk4);
            As[kk4 + 0][m] = fa.x; As[kk4 + 1][m] = fa.y;
            As[kk4 + 2][m] = fa.z; As[kk4 + 3][m] = fa.w;
            // B tile: 16 k x 128 n = 512 float4  (k = idx>>5, n4 = idx&31)
            int kk = idx >> 5, n4 = (idx & 31) << 2;
            *reinterpret_cast<float4*>(&Bs[kk][n4]) =
                *reinterpret_cast<const float4*>(Bm + (size_t)(k0 + kk) * N + bn + n4);
        }
        __syncthreads();

        #pragma unroll
        for (int kk = 0; kk < 16; kk++) {
            float4 a0 = *reinterpret_cast<const float4*>(&As[kk][ty * 8]);
            float4 a1 = *reinterpret_cast<const float4*>(&As[kk][ty * 8 + 4]);
            ulonglong2 bb0 = *reinterpret_cast<const ulonglong2*>(&Bs[kk][tx * 8]);
            ulonglong2 bb1 = *reinterpret_cast<const ulonglong2*>(&Bs[kk][tx * 8 + 4]);
            unsigned long long ad[8];
            ad[0] = pk2(a0.x); ad[1] = pk2(a0.y); ad[2] = pk2(a0.z); ad[3] = pk2(a0.w);
            ad[4] = pk2(a1.x); ad[5] = pk2(a1.y); ad[6] = pk2(a1.z); ad[7] = pk2(a1.w);
            #pragma unroll
            for (int i = 0; i < 8; i++) {
                fma2(acc[i][0], ad[i], bb0.x);
                fma2(acc[i][1], ad[i], bb0.y);
                fma2(acc[i][2], ad[i], bb1.x);
                fma2(acc[i][3], ad[i], bb1.y);
            }
        }
        __syncthreads();
    }

    float bs[8];
    #pragma unroll
    for (int j = 0; j < 8; j++) bs[j] = bias[bn + tx * 8 + j];

    #pragma unroll
    for (int i = 0; i < 8; i++) {
        float out[8];
        #pragma unroll
        for (int j = 0; j < 4; j++) {
            float lo, hi;
            asm("mov.b64 {%0, %1}, %2;" : "=f"(lo), "=f"(hi) : "l"(acc[i][j]));
            out[2 * j]     = lo + bs[2 * j];
            out[2 * j + 1] = hi + bs[2 * j + 1];
        }
        float* cp = C + (size_t)(bm + ty * 8 + i) * N + bn + tx * 8;
        *reinterpret_cast<float4*>(cp)     = make_float4(out[0], out[1], out[2], out[3]);
        *reinterpret_cast<float4*>(cp + 4) = make_float4(out[4], out[5], out[6], out[7]);
    }
}

// =============================================================================
// Flash attention per (b, h, l-tile of 64). q pre-scaled. Online softmax.
// smem tiles 64x64 fp32 with XOR swizzle (float4-granular) for conflict-free
// row-varying lane access. 256 threads; thread (ty,tx) owns S/O 4x4 block:
// rows r0=4*ty, cols t0/c0=4*tx.
// =============================================================================
#define SWZ(row, d4) ((((row) << 4)) + ((d4) ^ (((row) >> 2) & 15)))

__global__ __launch_bounds__(256)
void attn_kernel(const float* __restrict__ qbuf,   // [B*L, 512]
                 const float* __restrict__ kvbuf,  // [B*T, 1024]
                 float* __restrict__ obuf)         // [B*L, 512]
{
    extern __shared__ float sm[];
    float4* q4 = reinterpret_cast<float4*>(sm);
    float4* k4 = q4 + 1024;
    float4* v4 = k4 + 1024;
    float4* p4 = v4 + 1024;   // P^T: rows = t, cols = r
    float*  p_s = reinterpret_cast<float*>(p4);

    const int bid = blockIdx.x;         // b*32 + h*4 + lt
    const int lt = bid & 3;
    const int h  = (bid >> 2) & 7;
    const int b  = bid >> 5;
    const int tid = threadIdx.x;
    const int tx = tid & 15, ty = tid >> 4;
    const int r0 = ty * 4, c0 = tx * 4;
    const int l0 = lt * 64;

    // load Q tile [64 rows x 64 dims], pre-scaled by 1/8
    #pragma unroll
    for (int it = 0; it < 4; it++) {
        int idx = tid + it * 256;
        int r = idx >> 4, d4 = idx & 15;
        float4 f = *reinterpret_cast<const float4*>(
            qbuf + (size_t)(b * L_ + l0 + r) * D_ + h * 64 + d4 * 4);
        f.x *= 0.125f; f.y *= 0.125f; f.z *= 0.125f; f.w *= 0.125f;
        q4[SWZ(r, d4)] = f;
    }

    float m[4], lsum[4], O[4][4];
    #pragma unroll
    for (int i = 0; i < 4; i++) {
        m[i] = -CUDART_INF_F; lsum[i] = 0.f;
        #pragma unroll
        for (int j = 0; j < 4; j++) O[i][j] = 0.f;
    }

    for (int tc = 0; tc < T_; tc += 64) {
        __syncthreads();   // protects q (first iter) and k/v/p reuse (later iters)

        // load K,V chunk [64 x 64]
        #pragma unroll
        for (int it = 0; it < 4; it++) {
            int idx = tid + it * 256;
            int t = idx >> 4, d4 = idx & 15;
            const float* base =
                kvbuf + (size_t)(b * T_ + tc + t) * (2 * D_) + h * 64 + d4 * 4;
            k4[SWZ(t, d4)] = *reinterpret_cast<const float4*>(base);
            v4[SWZ(t, d4)] = *reinterpret_cast<const float4*>(base + D_);
        }
        __syncthreads();

        // S = Q K^T (4x4 per thread)
        float s[4][4];
        #pragma unroll
        for (int i = 0; i < 4; i++)
            #pragma unroll
            for (int j = 0; j < 4; j++) s[i][j] = 0.f;

        #pragma unroll
        for (int d4 = 0; d4 < 16; d4++) {
            float4 qv[4], kv[4];
            #pragma unroll
            for (int i = 0; i < 4; i++) qv[i] = q4[SWZ(r0 + i, d4)];
            #pragma unroll
            for (int j = 0; j < 4; j++) kv[j] = k4[SWZ(c0 + j, d4)];
            #pragma unroll
            for (int i = 0; i < 4; i++)
                #pragma unroll
                for (int j = 0; j < 4; j++)
                    s[i][j] += qv[i].x * kv[j].x + qv[i].y * kv[j].y
                             + qv[i].z * kv[j].z + qv[i].w * kv[j].w;
        }

        // online softmax (row groups = 16 consecutive lanes; xor 1,2,4,8)
        #pragma unroll
        for (int i = 0; i < 4; i++) {
            float mx = fmaxf(fmaxf(s[i][0], s[i][1]), fmaxf(s[i][2], s[i][3]));
            #pragma unroll
            for (int o = 8; o >= 1; o >>= 1)
                mx = fmaxf(mx, __shfl_xor_sync(0xffffffffu, mx, o));
            float mn = fmaxf(m[i], mx);
            float p0 = __expf(s[i][0] - mn), p1 = __expf(s[i][1] - mn);
            float p2 = __expf(s[i][2] - mn), p3 = __expf(s[i][3] - mn);
            float rs = p0 + p1 + p2 + p3;
            #pragma unroll
            for (int o = 8; o >= 1; o >>= 1)
                rs += __shfl_xor_sync(0xffffffffu, rs, o);
            float alpha = __expf(m[i] - mn);
            lsum[i] = lsum[i] * alpha + rs;
            m[i] = mn;
            #pragma unroll
            for (int j = 0; j < 4; j++) O[i][j] *= alpha;
            // write P^T[t][r]
            p_s[SWZ(c0 + 0, ty) * 4 + i] = p0;
            p_s[SWZ(c0 + 1, ty) * 4 + i] = p1;
            p_s[SWZ(c0 + 2, ty) * 4 + i] = p2;
            p_s[SWZ(c0 + 3, ty) * 4 + i] = p3;
        }
        __syncthreads();

        // O += P V (4x4 per thread; rows r0.., cols c0..)
        #pragma unroll 8
        for (int t = 0; t < 64; t++) {
            float4 pv = p4[SWZ(t, ty)];   // P^T[t][r0..r0+4]
            float4 vv = v4[SWZ(t, tx)];   // V[t][c0..c0+4]
            O[0][0] += pv.x * vv.x; O[0][1] += pv.x * vv.y; O[0][2] += pv.x * vv.z; O[0][3] += pv.x * vv.w;
            O[1][0] += pv.y * vv.x; O[1][1] += pv.y * vv.y; O[1][2] += pv.y * vv.z; O[1][3] += pv.y * vv.w;
            O[2][0] += pv.z * vv.x; O[2][1] += pv.z * vv.y; O[2][2] += pv.z * vv.z; O[2][3] += pv.z * vv.w;
            O[3][0] += pv.w * vv.x; O[3][1] += pv.w * vv.y; O[3][2] += pv.w * vv.z; O[3][3] += pv.w * vv.w;
        }
    }

    // epilogue: normalize, write [B*L, 512] with head offset
    #pragma unroll
    for (int i = 0; i < 4; i++) {
        float inv = 1.0f / lsum[i];
        float4 o = make_float4(O[i][0] * inv, O[i][1] * inv, O[i][2] * inv, O[i][3] * inv);
        *reinterpret_cast<float4*>(
            obuf + (size_t)(b * L_ + l0 + r0 + i) * D_ + h * 64 + c0) = o;
    }
}

// =============================================================================
// launch
// =============================================================================
extern "C" void kernel_launch(void* const* d_in, const int* in_sizes, int n_in,
                              void* d_out, int out_size)
{
    const float* x     = (const float*)d_in[0];
    const float* query = (const float*)d_in[1];
    const float* Wq    = (const float*)d_in[2];
    const float* bq    = (const float*)d_in[3];
    const float* Wkv   = (const float*)d_in[4];
    const float* bkv   = (const float*)d_in[5];
    const float* Wproj = (const float*)d_in[6];
    const float* bproj = (const float*)d_in[7];
    float* out = (float*)d_out;

    float *kv, *q, *att;
    cudaGetSymbolAddress((void**)&kv,  g_kv);
    cudaGetSymbolAddress((void**)&q,   g_q);
    cudaGetSymbolAddress((void**)&att, g_att);

    cudaFuncSetAttribute(attn_kernel,
                         cudaFuncAttributeMaxDynamicSharedMemorySize, 65536);

    // kv = x @ Wkv + bkv : [65536, 1024]
    sgemm_bias<<<dim3(1024 / 128, (B_ * T_) / 128), 256>>>(
        x, Wkv, bkv, kv, B_ * T_, 2 * D_, D_);
    // q = query @ Wq + bq : [2048, 512]
    sgemm_bias<<<dim3(D_ / 128, (B_ * L_) / 128), 256>>>(
        query, Wq, bq, q, B_ * L_, D_, D_);
    // attention -> att [2048, 512]
    attn_kernel<<<B_ * H_ * (L_ / 64), 256, 65536>>>(q, kv, att);
    // out = att @ Wproj + bproj : [2048, 512]
    sgemm_bias<<<dim3(D_ / 128, (B_ * L_) / 128), 256>>>(
        att, Wproj, bproj, out, B_ * L_, D_, D_);
}

// round 3
// speedup vs baseline: 1.6077x; 1.6077x over previous
#include <cuda_runtime.h>
#include <cuda_bf16.h>
#include <math_constants.h>
#include <cstdint>

// Problem constants
#define B_ 8
#define T_ 8192
#define L_ 256
#define D_ 512
#define H_ 8
// HD = 64, scale = 1/8

// ---------------- scratch (device globals; no allocs allowed) ----------------
__device__ float g_kv [(size_t)B_ * T_ * 2 * D_];  // [B*T, 1024]
__device__ float g_q  [(size_t)B_ * L_ * D_];      // [B*L, 512]
__device__ float g_att[(size_t)B_ * L_ * D_];      // [B*L, 512]

__device__ __nv_bfloat16 g_wkv_h[1024 * 512], g_wkv_l[1024 * 512];   // Wkv^T split
__device__ __nv_bfloat16 g_wq_h [512 * 512],  g_wq_l [512 * 512];    // Wq^T split
__device__ __nv_bfloat16 g_wp_h [512 * 512],  g_wp_l [512 * 512];    // Wproj^T split

__device__ __forceinline__ uint32_t smem_u32(const void* p) {
    uint32_t a;
    asm("{ .reg .u64 t; cvta.to.shared.u64 t, %1; cvt.u32.u64 %0, t; }"
        : "=r"(a) : "l"(p));
    return a;
}

#define LDSM4(r, addr) \
    asm volatile("ldmatrix.sync.aligned.m8n8.x4.shared.b16 {%0,%1,%2,%3}, [%4];" \
        : "=r"((r)[0]), "=r"((r)[1]), "=r"((r)[2]), "=r"((r)[3]) : "r"(addr))

#define MMA16816(d, a, b0r, b1r) \
    asm volatile("mma.sync.aligned.m16n8k16.row.col.f32.bf16.bf16.f32 " \
        "{%0,%1,%2,%3}, {%4,%5,%6,%7}, {%8,%9}, {%0,%1,%2,%3};" \
        : "+f"((d)[0]), "+f"((d)[1]), "+f"((d)[2]), "+f"((d)[3]) \
        : "r"((a)[0]), "r"((a)[1]), "r"((a)[2]), "r"((a)[3]), "r"(b0r), "r"(b1r))

// swizzle for 64-byte rows (4x16B segs): seg' = seg ^ ((row>>1)&3)
#define SWZ64(o) ((o) ^ ((((o) >> 7) & 3) << 4))

// =============================================================================
// Weight split/transpose: W[K,N] fp32 -> Wt_hi/Wt_lo [N,K] bf16
// =============================================================================
__global__ void split_w(const float* __restrict__ W, __nv_bfloat16* __restrict__ Th,
                        __nv_bfloat16* __restrict__ Tl, int K, int N)
{
    int idx = blockIdx.x * blockDim.x + threadIdx.x;
    if (idx >= K * N) return;
    int k = idx / N, n = idx % N;     // coalesced read of W
    float w = W[idx];
    __nv_bfloat16 h = __float2bfloat16_rn(w);
    float r = w - __bfloat162float(h);
    __nv_bfloat16 l = __float2bfloat16_rn(r);
    Th[(size_t)n * K + k] = h;
    Tl[(size_t)n * K + k] = l;
}

// =============================================================================
// HMMA GEMM: C[M,N] = A[M,K](fp32, split in-kernel) @ Wt^T + bias
// Wt given as [N,K] bf16 hi/lo. CTA tile 128x128, 8 warps (2x4), warp 64x32.
// K chunks of 32, double-buffered smem, register prefetch.
// Requires M%128==0, N%128==0, K%32==0.
// smem per stage: Ah(8K) Al(8K) Bh(8K) Bl(8K) = 32KB; two stages = 64KB.
// =============================================================================
#define GEMM_SMEM 65536

__global__ __launch_bounds__(256, 1)
void gemm_mma(const float* __restrict__ A, const __nv_bfloat16* __restrict__ Bth,
              const __nv_bfloat16* __restrict__ Btl, const float* __restrict__ bias,
              float* __restrict__ C, int M, int N, int K)
{
    extern __shared__ char smem[];
    const int tid  = threadIdx.x;
    const int lane = tid & 31;
    const int warp = tid >> 5;
    const int wm = warp >> 2;          // 0..1
    const int wn = warp & 3;           // 0..3
    const int bm = blockIdx.y * 128;
    const int bn = blockIdx.x * 128;

    float acc[4][4][4];
    #pragma unroll
    for (int i = 0; i < 4; i++)
        #pragma unroll
        for (int j = 0; j < 4; j++)
            #pragma unroll
            for (int k = 0; k < 4; k++) acc[i][j][k] = 0.f;

    const int nchunk = K >> 5;

    // prefetch registers
    float4 pa[4];
    uint4  pbh[2], pbl[2];

    // per-thread producer indices
    const int ar  = (tid * 4) >> 5;            // not used; explicit below
    (void)ar;

    // ---- global load of chunk c into regs ----
    auto loadg = [&](int c) {
        #pragma unroll
        for (int i = 0; i < 4; i++) {
            int idx = tid + i * 256;          // 0..1023
            int r = idx >> 3, k4 = idx & 7;
            pa[i] = *reinterpret_cast<const float4*>(
                A + (size_t)(bm + r) * K + c * 32 + k4 * 4);
        }
        #pragma unroll
        for (int i = 0; i < 2; i++) {
            int idx = tid + i * 256;          // 0..511
            int n = idx >> 2, s = idx & 3;
            const size_t go = (size_t)(bn + n) * K + c * 32 + s * 8;
            pbh[i] = *reinterpret_cast<const uint4*>(Bth + go);
            pbl[i] = *reinterpret_cast<const uint4*>(Btl + go);
        }
    };

    // ---- store prefetched regs into smem stage buf ----
    auto storeS = [&](int buf) {
        char* base = smem + buf * 32768;
        #pragma unroll
        for (int i = 0; i < 4; i++) {
            int idx = tid + i * 256;
            int r = idx >> 3, k4 = idx & 7;
            int off = r * 64 + k4 * 8;
            int sw = SWZ64(off);
            float4 v = pa[i];
            __nv_bfloat162 h01 = __floats2bfloat162_rn(v.x, v.y);
            __nv_bfloat162 h23 = __floats2bfloat162_rn(v.z, v.w);
            float2 f01 = __bfloat1622float2(h01);
            float2 f23 = __bfloat1622float2(h23);
            __nv_bfloat162 l01 = __floats2bfloat162_rn(v.x - f01.x, v.y - f01.y);
            __nv_bfloat162 l23 = __floats2bfloat162_rn(v.z - f23.x, v.w - f23.y);
            *reinterpret_cast<uint2*>(base + sw) =
                make_uint2(*(uint32_t*)&h01, *(uint32_t*)&h23);
            *reinterpret_cast<uint2*>(base + 8192 + sw) =
                make_uint2(*(uint32_t*)&l01, *(uint32_t*)&l23);
        }
        #pragma unroll
        for (int i = 0; i < 2; i++) {
            int idx = tid + i * 256;
            int n = idx >> 2, s = idx & 3;
            int off = n * 64 + s * 16;
            int sw = SWZ64(off);
            *reinterpret_cast<uint4*>(base + 16384 + sw) = pbh[i];
            *reinterpret_cast<uint4*>(base + 24576 + sw) = pbl[i];
        }
    };

    // ---- compute one chunk from smem stage buf ----
    const uint32_t sbase = smem_u32(smem);
    const uint32_t arow  = wm * 64 + (lane & 15);
    const uint32_t aoffb = arow * 64 + ((lane >> 4) << 4);
    const uint32_t axor  = ((arow >> 1) & 3) << 4;
    const uint32_t brow  = wn * 32 + (lane & 7) + ((lane >> 4) << 3);
    const uint32_t boffb = brow * 64 + (((lane >> 3) & 1) << 4);
    const uint32_t bxor  = ((brow >> 1) & 3) << 4;

    auto compute = [&](int buf) {
        const uint32_t sa = sbase + buf * 32768;
        #pragma unroll
        for (int ks = 0; ks < 2; ks++) {
            uint32_t Ah[4][4], Al[4][4];
            #pragma unroll
            for (int mt = 0; mt < 4; mt++) {
                uint32_t addr = (sa + aoffb + mt * 1024 + ks * 32) ^ axor;
                LDSM4(Ah[mt], addr);
                LDSM4(Al[mt], addr + 8192);
            }
            uint32_t Bh[2][4], Bl[2][4];
            #pragma unroll
            for (int np = 0; np < 2; np++) {
                uint32_t addr = (sa + 16384 + boffb + np * 1024 + ks * 32) ^ bxor;
                LDSM4(Bh[np], addr);
                LDSM4(Bl[np], addr + 8192);
            }
            #pragma unroll
            for (int mt = 0; mt < 4; mt++) {
                #pragma unroll
                for (int nt = 0; nt < 4; nt++) {
                    const int np = nt >> 1, bi = (nt & 1) * 2;
                    MMA16816(acc[mt][nt], Ah[mt], Bh[np][bi], Bh[np][bi + 1]);
                    MMA16816(acc[mt][nt], Ah[mt], Bl[np][bi], Bl[np][bi + 1]);
                    MMA16816(acc[mt][nt], Al[mt], Bh[np][bi], Bh[np][bi + 1]);
                }
            }
        }
    };

    loadg(0);
    storeS(0);
    __syncthreads();
    for (int c = 0; c < nchunk; c++) {
        if (c + 1 < nchunk) loadg(c + 1);
        compute(c & 1);
        if (c + 1 < nchunk) {
            storeS((c + 1) & 1);
            __syncthreads();
        }
    }

    // ---- epilogue: direct stores (32B sectors), bias added ----
    #pragma unroll
    for (int nt = 0; nt < 4; nt++) {
        const int ncol = bn + wn * 32 + nt * 8 + 2 * (lane & 3);
        const float2 bb = *reinterpret_cast<const float2*>(bias + ncol);
        #pragma unroll
        for (int mt = 0; mt < 4; mt++) {
            const int m0 = bm + wm * 64 + mt * 16 + (lane >> 2);
            float* p0 = C + (size_t)m0 * N + ncol;
            float* p1 = C + (size_t)(m0 + 8) * N + ncol;
            *reinterpret_cast<float2*>(p0) =
                make_float2(acc[mt][nt][0] + bb.x, acc[mt][nt][1] + bb.y);
            *reinterpret_cast<float2*>(p1) =
                make_float2(acc[mt][nt][2] + bb.x, acc[mt][nt][3] + bb.y);
        }
    }
}

// =============================================================================
// Flash attention per (b, h, l-tile of 64). Unchanged (proven correct, R1).
// =============================================================================
#define SWZ(row, d4) ((((row) << 4)) + ((d4) ^ (((row) >> 2) & 15)))

__global__ __launch_bounds__(256)
void attn_kernel(const float* __restrict__ qbuf,   // [B*L, 512]
                 const float* __restrict__ kvbuf,  // [B*T, 1024]
                 float* __restrict__ obuf)         // [B*L, 512]
{
    extern __shared__ float sm[];
    float4* q4 = reinterpret_cast<float4*>(sm);
    float4* k4 = q4 + 1024;
    float4* v4 = k4 + 1024;
    float4* p4 = v4 + 1024;
    float*  p_s = reinterpret_cast<float*>(p4);

    const int bid = blockIdx.x;
    const int lt = bid & 3;
    const int h  = (bid >> 2) & 7;
    const int b  = bid >> 5;
    const int tid = threadIdx.x;
    const int tx = tid & 15, ty = tid >> 4;
    const int r0 = ty * 4, c0 = tx * 4;
    const int l0 = lt * 64;

    #pragma unroll
    for (int it = 0; it < 4; it++) {
        int idx = tid + it * 256;
        int r = idx >> 4, d4 = idx & 15;
        float4 f = *reinterpret_cast<const float4*>(
            qbuf + (size_t)(b * L_ + l0 + r) * D_ + h * 64 + d4 * 4);
        f.x *= 0.125f; f.y *= 0.125f; f.z *= 0.125f; f.w *= 0.125f;
        q4[SWZ(r, d4)] = f;
    }

    float m[4], lsum[4], O[4][4];
    #pragma unroll
    for (int i = 0; i < 4; i++) {
        m[i] = -CUDART_INF_F; lsum[i] = 0.f;
        #pragma unroll
        for (int j = 0; j < 4; j++) O[i][j] = 0.f;
    }

    for (int tc = 0; tc < T_; tc += 64) {
        __syncthreads();
        #pragma unroll
        for (int it = 0; it < 4; it++) {
            int idx = tid + it * 256;
            int t = idx >> 4, d4 = idx & 15;
            const float* base =
                kvbuf + (size_t)(b * T_ + tc + t) * (2 * D_) + h * 64 + d4 * 4;
            k4[SWZ(t, d4)] = *reinterpret_cast<const float4*>(base);
            v4[SWZ(t, d4)] = *reinterpret_cast<const float4*>(base + D_);
        }
        __syncthreads();

        float s[4][4];
        #pragma unroll
        for (int i = 0; i < 4; i++)
            #pragma unroll
            for (int j = 0; j < 4; j++) s[i][j] = 0.f;

        #pragma unroll
        for (int d4 = 0; d4 < 16; d4++) {
            float4 qv[4], kv[4];
            #pragma unroll
            for (int i = 0; i < 4; i++) qv[i] = q4[SWZ(r0 + i, d4)];
            #pragma unroll
            for (int j = 0; j < 4; j++) kv[j] = k4[SWZ(c0 + j, d4)];
            #pragma unroll
            for (int i = 0; i < 4; i++)
                #pragma unroll
                for (int j = 0; j < 4; j++)
                    s[i][j] += qv[i].x * kv[j].x + qv[i].y * kv[j].y
                             + qv[i].z * kv[j].z + qv[i].w * kv[j].w;
        }

        #pragma unroll
        for (int i = 0; i < 4; i++) {
            float mx = fmaxf(fmaxf(s[i][0], s[i][1]), fmaxf(s[i][2], s[i][3]));
            #pragma unroll
            for (int o = 8; o >= 1; o >>= 1)
                mx = fmaxf(mx, __shfl_xor_sync(0xffffffffu, mx, o));
            float mn = fmaxf(m[i], mx);
            float p0 = __expf(s[i][0] - mn), p1 = __expf(s[i][1] - mn);
            float p2 = __expf(s[i][2] - mn), p3 = __expf(s[i][3] - mn);
            float rs = p0 + p1 + p2 + p3;
            #pragma unroll
            for (int o = 8; o >= 1; o >>= 1)
                rs += __shfl_xor_sync(0xffffffffu, rs, o);
            float alpha = __expf(m[i] - mn);
            lsum[i] = lsum[i] * alpha + rs;
            m[i] = mn;
            #pragma unroll
            for (int j = 0; j < 4; j++) O[i][j] *= alpha;
            p_s[SWZ(c0 + 0, ty) * 4 + i] = p0;
            p_s[SWZ(c0 + 1, ty) * 4 + i] = p1;
            p_s[SWZ(c0 + 2, ty) * 4 + i] = p2;
            p_s[SWZ(c0 + 3, ty) * 4 + i] = p3;
        }
        __syncthreads();

        #pragma unroll 8
        for (int t = 0; t < 64; t++) {
            float4 pv = p4[SWZ(t, ty)];
            float4 vv = v4[SWZ(t, tx)];
            O[0][0] += pv.x * vv.x; O[0][1] += pv.x * vv.y; O[0][2] += pv.x * vv.z; O[0][3] += pv.x * vv.w;
            O[1][0] += pv.y * vv.x; O[1][1] += pv.y * vv.y; O[1][2] += pv.y * vv.z; O[1][3] += pv.y * vv.w;
            O[2][0] += pv.z * vv.x; O[2][1] += pv.z * vv.y; O[2][2] += pv.z * vv.z; O[2][3] += pv.z * vv.w;
            O[3][0] += pv.w * vv.x; O[3][1] += pv.w * vv.y; O[3][2] += pv.w * vv.z; O[3][3] += pv.w * vv.w;
        }
    }

    #pragma unroll
    for (int i = 0; i < 4; i++) {
        float inv = 1.0f / lsum[i];
        float4 o = make_float4(O[i][0] * inv, O[i][1] * inv, O[i][2] * inv, O[i][3] * inv);
        *reinterpret_cast<float4*>(
            obuf + (size_t)(b * L_ + l0 + r0 + i) * D_ + h * 64 + c0) = o;
    }
}

// =============================================================================
// launch
// =============================================================================
extern "C" void kernel_launch(void* const* d_in, const int* in_sizes, int n_in,
                              void* d_out, int out_size)
{
    const float* x     = (const float*)d_in[0];
    const float* query = (const float*)d_in[1];
    const float* Wq    = (const float*)d_in[2];
    const float* bq    = (const float*)d_in[3];
    const float* Wkv   = (const float*)d_in[4];
    const float* bkv   = (const float*)d_in[5];
    const float* Wproj = (const float*)d_in[6];
    const float* bproj = (const float*)d_in[7];
    float* out = (float*)d_out;

    float *kv, *q, *att;
    cudaGetSymbolAddress((void**)&kv,  g_kv);
    cudaGetSymbolAddress((void**)&q,   g_q);
    cudaGetSymbolAddress((void**)&att, g_att);
    __nv_bfloat16 *wkvh, *wkvl, *wqh, *wql, *wph, *wpl;
    cudaGetSymbolAddress((void**)&wkvh, g_wkv_h);
    cudaGetSymbolAddress((void**)&wkvl, g_wkv_l);
    cudaGetSymbolAddress((void**)&wqh,  g_wq_h);
    cudaGetSymbolAddress((void**)&wql,  g_wq_l);
    cudaGetSymbolAddress((void**)&wph,  g_wp_h);
    cudaGetSymbolAddress((void**)&wpl,  g_wp_l);

    cudaFuncSetAttribute(gemm_mma,
                         cudaFuncAttributeMaxDynamicSharedMemorySize, GEMM_SMEM);
    cudaFuncSetAttribute(attn_kernel,
                         cudaFuncAttributeMaxDynamicSharedMemorySize, 65536);

    // weight transpose+split
    split_w<<<(512 * 1024 + 255) / 256, 256>>>(Wkv,   wkvh, wkvl, 512, 1024);
    split_w<<<(512 * 512  + 255) / 256, 256>>>(Wq,    wqh,  wql,  512, 512);
    split_w<<<(512 * 512  + 255) / 256, 256>>>(Wproj, wph,  wpl,  512, 512);

    // kv = x @ Wkv + bkv : [65536, 1024]
    gemm_mma<<<dim3(1024 / 128, (B_ * T_) / 128), 256, GEMM_SMEM>>>(
        x, wkvh, wkvl, bkv, kv, B_ * T_, 2 * D_, D_);
    // q = query @ Wq + bq : [2048, 512]
    gemm_mma<<<dim3(D_ / 128, (B_ * L_) / 128), 256, GEMM_SMEM>>>(
        query, wqh, wql, bq, q, B_ * L_, D_, D_);
    // attention -> att [2048, 512]
    attn_kernel<<<B_ * H_ * (L_ / 64), 256, 65536>>>(q, kv, att);
    // out = att @ Wproj + bproj : [2048, 512]
    gemm_mma<<<dim3(D_ / 128, (B_ * L_) / 128), 256, GEMM_SMEM>>>(
        att, wph, wpl, bproj, out, B_ * L_, D_, D_);
}

// round 4
// speedup vs baseline: 2.9212x; 1.8170x over previous
#include <cuda_runtime.h>
#include <cuda_bf16.h>
#include <math_constants.h>
#include <cstdint>

// Problem constants
#define B_ 8
#define T_ 8192
#define L_ 256
#define D_ 512
#define H_ 8
// HD = 64, scale = 1/8

// ---------------- scratch (device globals; no allocs allowed) ----------------
__device__ float g_kv [(size_t)B_ * T_ * 2 * D_];  // [B*T, 1024]
__device__ float g_q  [(size_t)B_ * L_ * D_];      // [B*L, 512]
__device__ float g_att[(size_t)B_ * L_ * D_];      // [B*L, 512]

__device__ __nv_bfloat16 g_wkv_h[1024 * 512], g_wkv_l[1024 * 512];   // Wkv^T split
__device__ __nv_bfloat16 g_wq_h [512 * 512],  g_wq_l [512 * 512];    // Wq^T split
__device__ __nv_bfloat16 g_wp_h [512 * 512],  g_wp_l [512 * 512];    // Wproj^T split

__device__ __forceinline__ uint32_t smem_u32(const void* p) {
    uint32_t a;
    asm("{ .reg .u64 t; cvta.to.shared.u64 t, %1; cvt.u32.u64 %0, t; }"
        : "=r"(a) : "l"(p));
    return a;
}

#define LDSM4(r, addr) \
    asm volatile("ldmatrix.sync.aligned.m8n8.x4.shared.b16 {%0,%1,%2,%3}, [%4];" \
        : "=r"((r)[0]), "=r"((r)[1]), "=r"((r)[2]), "=r"((r)[3]) : "r"(addr))
#define LDSM4T(r, addr) \
    asm volatile("ldmatrix.sync.aligned.m8n8.x4.trans.shared.b16 {%0,%1,%2,%3}, [%4];" \
        : "=r"((r)[0]), "=r"((r)[1]), "=r"((r)[2]), "=r"((r)[3]) : "r"(addr))

#define MMA16816(d, a, b0r, b1r) \
    asm volatile("mma.sync.aligned.m16n8k16.row.col.f32.bf16.bf16.f32 " \
        "{%0,%1,%2,%3}, {%4,%5,%6,%7}, {%8,%9}, {%0,%1,%2,%3};" \
        : "+f"((d)[0]), "+f"((d)[1]), "+f"((d)[2]), "+f"((d)[3]) \
        : "r"((a)[0]), "r"((a)[1]), "r"((a)[2]), "r"((a)[3]), "r"(b0r), "r"(b1r))

// swizzle for 64-byte rows (4x16B segs)
#define SWZ64(o) ((o) ^ ((((o) >> 7) & 3) << 4))
// swizzle for 128-byte rows (8x16B segs)
#define SWZ128(o) ((o) ^ ((((o) >> 7) & 7) << 4))

// =============================================================================
// Weight split/transpose: W[K,N] fp32 -> Wt_hi/Wt_lo [N,K] bf16
// =============================================================================
__global__ void split_w(const float* __restrict__ W, __nv_bfloat16* __restrict__ Th,
                        __nv_bfloat16* __restrict__ Tl, int K, int N)
{
    int idx = blockIdx.x * blockDim.x + threadIdx.x;
    if (idx >= K * N) return;
    int k = idx / N, n = idx % N;     // coalesced read of W
    float w = W[idx];
    __nv_bfloat16 h = __float2bfloat16_rn(w);
    float r = w - __bfloat162float(h);
    __nv_bfloat16 l = __float2bfloat16_rn(r);
    Th[(size_t)n * K + k] = h;
    Tl[(size_t)n * K + k] = l;
}

// =============================================================================
// HMMA GEMM (unchanged from R3): C = A @ Wt^T + bias, 128x128 tile, 8 warps.
// =============================================================================
#define GEMM_SMEM 65536

__global__ __launch_bounds__(256, 1)
void gemm_mma(const float* __restrict__ A, const __nv_bfloat16* __restrict__ Bth,
              const __nv_bfloat16* __restrict__ Btl, const float* __restrict__ bias,
              float* __restrict__ C, int M, int N, int K)
{
    extern __shared__ char smem[];
    const int tid  = threadIdx.x;
    const int lane = tid & 31;
    const int warp = tid >> 5;
    const int wm = warp >> 2;
    const int wn = warp & 3;
    const int bm = blockIdx.y * 128;
    const int bn = blockIdx.x * 128;

    float acc[4][4][4];
    #pragma unroll
    for (int i = 0; i < 4; i++)
        #pragma unroll
        for (int j = 0; j < 4; j++)
            #pragma unroll
            for (int k = 0; k < 4; k++) acc[i][j][k] = 0.f;

    const int nchunk = K >> 5;
    float4 pa[4];
    uint4  pbh[2], pbl[2];

    auto loadg = [&](int c) {
        #pragma unroll
        for (int i = 0; i < 4; i++) {
            int idx = tid + i * 256;
            int r = idx >> 3, k4 = idx & 7;
            pa[i] = *reinterpret_cast<const float4*>(
                A + (size_t)(bm + r) * K + c * 32 + k4 * 4);
        }
        #pragma unroll
        for (int i = 0; i < 2; i++) {
            int idx = tid + i * 256;
            int n = idx >> 2, s = idx & 3;
            const size_t go = (size_t)(bn + n) * K + c * 32 + s * 8;
            pbh[i] = *reinterpret_cast<const uint4*>(Bth + go);
            pbl[i] = *reinterpret_cast<const uint4*>(Btl + go);
        }
    };

    auto storeS = [&](int buf) {
        char* base = smem + buf * 32768;
        #pragma unroll
        for (int i = 0; i < 4; i++) {
            int idx = tid + i * 256;
            int r = idx >> 3, k4 = idx & 7;
            int off = r * 64 + k4 * 8;
            int sw = SWZ64(off);
            float4 v = pa[i];
            __nv_bfloat162 h01 = __floats2bfloat162_rn(v.x, v.y);
            __nv_bfloat162 h23 = __floats2bfloat162_rn(v.z, v.w);
            float2 f01 = __bfloat1622float2(h01);
            float2 f23 = __bfloat1622float2(h23);
            __nv_bfloat162 l01 = __floats2bfloat162_rn(v.x - f01.x, v.y - f01.y);
            __nv_bfloat162 l23 = __floats2bfloat162_rn(v.z - f23.x, v.w - f23.y);
            *reinterpret_cast<uint2*>(base + sw) =
                make_uint2(*(uint32_t*)&h01, *(uint32_t*)&h23);
            *reinterpret_cast<uint2*>(base + 8192 + sw) =
                make_uint2(*(uint32_t*)&l01, *(uint32_t*)&l23);
        }
        #pragma unroll
        for (int i = 0; i < 2; i++) {
            int idx = tid + i * 256;
            int n = idx >> 2, s = idx & 3;
            int off = n * 64 + s * 16;
            int sw = SWZ64(off);
            *reinterpret_cast<uint4*>(base + 16384 + sw) = pbh[i];
            *reinterpret_cast<uint4*>(base + 24576 + sw) = pbl[i];
        }
    };

    const uint32_t sbase = smem_u32(smem);
    const uint32_t arow  = wm * 64 + (lane & 15);
    const uint32_t aoffb = arow * 64 + ((lane >> 4) << 4);
    const uint32_t axor  = ((arow >> 1) & 3) << 4;
    const uint32_t brow  = wn * 32 + (lane & 7) + ((lane >> 4) << 3);
    const uint32_t boffb = brow * 64 + (((lane >> 3) & 1) << 4);
    const uint32_t bxor  = ((brow >> 1) & 3) << 4;

    auto compute = [&](int buf) {
        const uint32_t sa = sbase + buf * 32768;
        #pragma unroll
        for (int ks = 0; ks < 2; ks++) {
            uint32_t Ah[4][4], Al[4][4];
            #pragma unroll
            for (int mt = 0; mt < 4; mt++) {
                uint32_t addr = (sa + aoffb + mt * 1024 + ks * 32) ^ axor;
                LDSM4(Ah[mt], addr);
                LDSM4(Al[mt], addr + 8192);
            }
            uint32_t Bh[2][4], Bl[2][4];
            #pragma unroll
            for (int np = 0; np < 2; np++) {
                uint32_t addr = (sa + 16384 + boffb + np * 1024 + ks * 32) ^ bxor;
                LDSM4(Bh[np], addr);
                LDSM4(Bl[np], addr + 8192);
            }
            #pragma unroll
            for (int mt = 0; mt < 4; mt++) {
                #pragma unroll
                for (int nt = 0; nt < 4; nt++) {
                    const int np = nt >> 1, bi = (nt & 1) * 2;
                    MMA16816(acc[mt][nt], Ah[mt], Bh[np][bi], Bh[np][bi + 1]);
                    MMA16816(acc[mt][nt], Ah[mt], Bl[np][bi], Bl[np][bi + 1]);
                    MMA16816(acc[mt][nt], Al[mt], Bh[np][bi], Bh[np][bi + 1]);
                }
            }
        }
    };

    loadg(0);
    storeS(0);
    __syncthreads();
    for (int c = 0; c < nchunk; c++) {
        if (c + 1 < nchunk) loadg(c + 1);
        compute(c & 1);
        if (c + 1 < nchunk) {
            storeS((c + 1) & 1);
            __syncthreads();
        }
    }

    #pragma unroll
    for (int nt = 0; nt < 4; nt++) {
        const int ncol = bn + wn * 32 + nt * 8 + 2 * (lane & 3);
        const float2 bb = *reinterpret_cast<const float2*>(bias + ncol);
        #pragma unroll
        for (int mt = 0; mt < 4; mt++) {
            const int m0 = bm + wm * 64 + mt * 16 + (lane >> 2);
            float* p0 = C + (size_t)m0 * N + ncol;
            float* p1 = C + (size_t)(m0 + 8) * N + ncol;
            *reinterpret_cast<float2*>(p0) =
                make_float2(acc[mt][nt][0] + bb.x, acc[mt][nt][1] + bb.y);
            *reinterpret_cast<float2*>(p1) =
                make_float2(acc[mt][nt][2] + bb.x, acc[mt][nt][3] + bb.y);
        }
    }
}

// =============================================================================
// HMMA flash attention. Grid = B*H*(L/128) = 128 CTAs, 8 warps, 16 Q-rows/warp.
// Q pre-scaled by 0.125*log2(e); softmax via exp2f. bf16 hi/lo 3-split for
// QK^T and PV. K/V converted fp32->bf16 hi/lo in-kernel per 64-step chunk.
// smem 32KB: [Kh 8K][Kl 8K][Vh 8K][Vl 8K]; prologue aliases it as Qh/Ql 16K+16K.
// =============================================================================
__global__ __launch_bounds__(256, 1)
void attn_mma(const float* __restrict__ qbuf,   // [B*L, 512]
              const float* __restrict__ kvbuf,  // [B*T, 1024]
              float* __restrict__ obuf)         // [B*L, 512]
{
    __shared__ char sm[32768];
    const uint32_t sb = smem_u32(sm);
    const int tid = threadIdx.x, lane = tid & 31, warp = tid >> 5;
    const int bid = blockIdx.x;          // b*16 + h*2 + lt
    const int lt = bid & 1;
    const int h  = (bid >> 1) & 7;
    const int b  = bid >> 4;
    const int l0 = lt * 128;

    // ---- Q prologue: load, scale, split hi/lo into smem (Qh @0, Ql @16K) ----
    const float cscale = 0.125f * 1.4426950408889634f;
    #pragma unroll
    for (int i = 0; i < 8; i++) {
        int idx = tid + i * 256;            // 2048 float4
        int r = idx >> 4, c4 = idx & 15;
        float4 v = *reinterpret_cast<const float4*>(
            qbuf + (size_t)(b * L_ + l0 + r) * D_ + h * 64 + c4 * 4);
        v.x *= cscale; v.y *= cscale; v.z *= cscale; v.w *= cscale;
        __nv_bfloat162 h01 = __floats2bfloat162_rn(v.x, v.y);
        __nv_bfloat162 h23 = __floats2bfloat162_rn(v.z, v.w);
        float2 f01 = __bfloat1622float2(h01);
        float2 f23 = __bfloat1622float2(h23);
        __nv_bfloat162 l01 = __floats2bfloat162_rn(v.x - f01.x, v.y - f01.y);
        __nv_bfloat162 l23 = __floats2bfloat162_rn(v.z - f23.x, v.w - f23.y);
        int off = r * 128 + c4 * 8;
        int sw = SWZ128(off);
        *reinterpret_cast<uint2*>(sm + sw) =
            make_uint2(*(uint32_t*)&h01, *(uint32_t*)&h23);
        *reinterpret_cast<uint2*>(sm + 16384 + sw) =
            make_uint2(*(uint32_t*)&l01, *(uint32_t*)&l23);
    }
    __syncthreads();

    // ---- load Q A-fragments into registers (held for entire loop) ----
    uint32_t Qh[4][4], Ql[4][4];
    {
        const int arow = warp * 16 + (lane & 15);
        const uint32_t abase = sb + arow * 128;
        const uint32_t axor = (arow & 7) << 4;
        #pragma unroll
        for (int kc = 0; kc < 4; kc++) {
            uint32_t o = ((((uint32_t)(lane >> 4) << 4) + kc * 32) ^ axor);
            LDSM4(Qh[kc], abase + o);
            LDSM4(Ql[kc], abase + 16384 + o);
        }
    }
    __syncthreads();

    float mrow[2] = { -CUDART_INF_F, -CUDART_INF_F };
    float lsum[2] = { 0.f, 0.f };
    float O[8][4];
    #pragma unroll
    for (int i = 0; i < 8; i++)
        #pragma unroll
        for (int j = 0; j < 4; j++) O[i][j] = 0.f;

    // K/V producer state
    float4 pk[4], pv[4];
    auto loadg = [&](int c) {
        #pragma unroll
        for (int i = 0; i < 4; i++) {
            int idx = tid + i * 256;        // 1024 slots: 64 rows x 16 float4
            int r = idx >> 4, c4 = idx & 15;
            const float* base =
                kvbuf + (size_t)(b * T_ + c * 64 + r) * 1024 + h * 64 + c4 * 4;
            pk[i] = *reinterpret_cast<const float4*>(base);
            pv[i] = *reinterpret_cast<const float4*>(base + 512);
        }
    };
    auto storeS = [&]() {
        #pragma unroll
        for (int i = 0; i < 4; i++) {
            int idx = tid + i * 256;
            int r = idx >> 4, c4 = idx & 15;
            int off = r * 128 + c4 * 8;
            int sw = SWZ128(off);
            {
                float4 v = pk[i];
                __nv_bfloat162 h01 = __floats2bfloat162_rn(v.x, v.y);
                __nv_bfloat162 h23 = __floats2bfloat162_rn(v.z, v.w);
                float2 f01 = __bfloat1622float2(h01);
                float2 f23 = __bfloat1622float2(h23);
                __nv_bfloat162 l01 = __floats2bfloat162_rn(v.x - f01.x, v.y - f01.y);
                __nv_bfloat162 l23 = __floats2bfloat162_rn(v.z - f23.x, v.w - f23.y);
                *reinterpret_cast<uint2*>(sm + sw) =
                    make_uint2(*(uint32_t*)&h01, *(uint32_t*)&h23);
                *reinterpret_cast<uint2*>(sm + 8192 + sw) =
                    make_uint2(*(uint32_t*)&l01, *(uint32_t*)&l23);
            }
            {
                float4 v = pv[i];
                __nv_bfloat162 h01 = __floats2bfloat162_rn(v.x, v.y);
                __nv_bfloat162 h23 = __floats2bfloat162_rn(v.z, v.w);
                float2 f01 = __bfloat1622float2(h01);
                float2 f23 = __bfloat1622float2(h23);
                __nv_bfloat162 l01 = __floats2bfloat162_rn(v.x - f01.x, v.y - f01.y);
                __nv_bfloat162 l23 = __floats2bfloat162_rn(v.z - f23.x, v.w - f23.y);
                *reinterpret_cast<uint2*>(sm + 16384 + sw) =
                    make_uint2(*(uint32_t*)&h01, *(uint32_t*)&h23);
                *reinterpret_cast<uint2*>(sm + 24576 + sw) =
                    make_uint2(*(uint32_t*)&l01, *(uint32_t*)&l23);
            }
        }
    };

    // B-fragment lane indices (QK: K rows are n; PV: V rows are k, trans)
    const int klrow = (lane & 7) + ((lane >> 4) << 3);
    const uint32_t kseg = ((uint32_t)((lane >> 3) & 1)) << 4;
    const int vlrow = (lane & 7) + (((lane >> 3) & 1) << 3);
    const int vseg_half = lane >> 4;

    loadg(0);
    for (int c = 0; c < T_ / 64; c++) {
        __syncthreads();
        storeS();
        __syncthreads();
        if (c + 1 < T_ / 64) loadg(c + 1);

        // ---- S = Q K^T (3-split) ----
        float S[8][4];
        #pragma unroll
        for (int i = 0; i < 8; i++)
            #pragma unroll
            for (int j = 0; j < 4; j++) S[i][j] = 0.f;

        #pragma unroll
        for (int np = 0; np < 4; np++) {
            const int brow = np * 16 + klrow;
            const uint32_t bbase = sb + brow * 128;
            const uint32_t bxor = (brow & 7) << 4;
            #pragma unroll
            for (int kc = 0; kc < 4; kc++) {
                uint32_t o = ((kseg + kc * 32) ^ bxor);
                uint32_t Bh[4], Bl[4];
                LDSM4(Bh, bbase + o);
                LDSM4(Bl, bbase + 8192 + o);
                MMA16816(S[2 * np],     Qh[kc], Bh[0], Bh[1]);
                MMA16816(S[2 * np],     Qh[kc], Bl[0], Bl[1]);
                MMA16816(S[2 * np],     Ql[kc], Bh[0], Bh[1]);
                MMA16816(S[2 * np + 1], Qh[kc], Bh[2], Bh[3]);
                MMA16816(S[2 * np + 1], Qh[kc], Bl[2], Bl[3]);
                MMA16816(S[2 * np + 1], Ql[kc], Bh[2], Bh[3]);
            }
        }

        // ---- online softmax (rows rowA = lane>>2, rowB = rowA+8) ----
        float mxA = -CUDART_INF_F, mxB = -CUDART_INF_F;
        #pragma unroll
        for (int nt = 0; nt < 8; nt++) {
            mxA = fmaxf(mxA, fmaxf(S[nt][0], S[nt][1]));
            mxB = fmaxf(mxB, fmaxf(S[nt][2], S[nt][3]));
        }
        #pragma unroll
        for (int o = 1; o <= 2; o <<= 1) {
            mxA = fmaxf(mxA, __shfl_xor_sync(0xffffffffu, mxA, o));
            mxB = fmaxf(mxB, __shfl_xor_sync(0xffffffffu, mxB, o));
        }
        const float mnA = fmaxf(mrow[0], mxA);
        const float mnB = fmaxf(mrow[1], mxB);
        const float alphaA = exp2f(mrow[0] - mnA);
        const float alphaB = exp2f(mrow[1] - mnB);
        mrow[0] = mnA; mrow[1] = mnB;

        uint32_t Ph[4][4], Pl[4][4];
        float sumA = 0.f, sumB = 0.f;
        #pragma unroll
        for (int nt = 0; nt < 8; nt++) {
            float p0 = exp2f(S[nt][0] - mnA);
            float p1 = exp2f(S[nt][1] - mnA);
            float p2 = exp2f(S[nt][2] - mnB);
            float p3 = exp2f(S[nt][3] - mnB);
            sumA += p0 + p1; sumB += p2 + p3;
            __nv_bfloat162 hA = __floats2bfloat162_rn(p0, p1);
            __nv_bfloat162 hB = __floats2bfloat162_rn(p2, p3);
            float2 fA = __bfloat1622float2(hA);
            float2 fB = __bfloat1622float2(hB);
            __nv_bfloat162 lA = __floats2bfloat162_rn(p0 - fA.x, p1 - fA.y);
            __nv_bfloat162 lB = __floats2bfloat162_rn(p2 - fB.x, p3 - fB.y);
            const int kc = nt >> 1, ri = (nt & 1) * 2;
            Ph[kc][ri]     = *(uint32_t*)&hA;
            Ph[kc][ri + 1] = *(uint32_t*)&hB;
            Pl[kc][ri]     = *(uint32_t*)&lA;
            Pl[kc][ri + 1] = *(uint32_t*)&lB;
        }
        #pragma unroll
        for (int o = 1; o <= 2; o <<= 1) {
            sumA += __shfl_xor_sync(0xffffffffu, sumA, o);
            sumB += __shfl_xor_sync(0xffffffffu, sumB, o);
        }
        lsum[0] = lsum[0] * alphaA + sumA;
        lsum[1] = lsum[1] * alphaB + sumB;
        #pragma unroll
        for (int nt = 0; nt < 8; nt++) {
            O[nt][0] *= alphaA; O[nt][1] *= alphaA;
            O[nt][2] *= alphaB; O[nt][3] *= alphaB;
        }

        // ---- O += P V (3-split), V via ldmatrix.trans ----
        #pragma unroll
        for (int kc = 0; kc < 4; kc++) {
            const int vrow = kc * 16 + vlrow;
            const uint32_t vbase = sb + 16384 + vrow * 128;
            const uint32_t vxor = (vrow & 7) << 4;
            #pragma unroll
            for (int ng = 0; ng < 4; ng++) {
                uint32_t o = ((uint32_t)((2 * ng + vseg_half) << 4)) ^ vxor;
                uint32_t Vh[4], Vl[4];
                LDSM4T(Vh, vbase + o);
                LDSM4T(Vl, vbase + 8192 + o);
                MMA16816(O[2 * ng],     Ph[kc], Vh[0], Vh[1]);
                MMA16816(O[2 * ng],     Ph[kc], Vl[0], Vl[1]);
                MMA16816(O[2 * ng],     Pl[kc], Vh[0], Vh[1]);
                MMA16816(O[2 * ng + 1], Ph[kc], Vh[2], Vh[3]);
                MMA16816(O[2 * ng + 1], Ph[kc], Vl[2], Vl[3]);
                MMA16816(O[2 * ng + 1], Pl[kc], Vh[2], Vh[3]);
            }
        }
    }

    // ---- epilogue: normalize rows, store ----
    const float invA = 1.0f / lsum[0];
    const float invB = 1.0f / lsum[1];
    const int rowA = b * L_ + l0 + warp * 16 + (lane >> 2);
    #pragma unroll
    for (int nt = 0; nt < 8; nt++) {
        const int col = h * 64 + nt * 8 + (lane & 3) * 2;
        *reinterpret_cast<float2*>(obuf + (size_t)rowA * D_ + col) =
            make_float2(O[nt][0] * invA, O[nt][1] * invA);
        *reinterpret_cast<float2*>(obuf + (size_t)(rowA + 8) * D_ + col) =
            make_float2(O[nt][2] * invB, O[nt][3] * invB);
    }
}

// =============================================================================
// launch
// =============================================================================
extern "C" void kernel_launch(void* const* d_in, const int* in_sizes, int n_in,
                              void* d_out, int out_size)
{
    const float* x     = (const float*)d_in[0];
    const float* query = (const float*)d_in[1];
    const float* Wq    = (const float*)d_in[2];
    const float* bq    = (const float*)d_in[3];
    const float* Wkv   = (const float*)d_in[4];
    const float* bkv   = (const float*)d_in[5];
    const float* Wproj = (const float*)d_in[6];
    const float* bproj = (const float*)d_in[7];
    float* out = (float*)d_out;

    float *kv, *q, *att;
    cudaGetSymbolAddress((void**)&kv,  g_kv);
    cudaGetSymbolAddress((void**)&q,   g_q);
    cudaGetSymbolAddress((void**)&att, g_att);
    __nv_bfloat16 *wkvh, *wkvl, *wqh, *wql, *wph, *wpl;
    cudaGetSymbolAddress((void**)&wkvh, g_wkv_h);
    cudaGetSymbolAddress((void**)&wkvl, g_wkv_l);
    cudaGetSymbolAddress((void**)&wqh,  g_wq_h);
    cudaGetSymbolAddress((void**)&wql,  g_wq_l);
    cudaGetSymbolAddress((void**)&wph,  g_wp_h);
    cudaGetSymbolAddress((void**)&wpl,  g_wp_l);

    cudaFuncSetAttribute(gemm_mma,
                         cudaFuncAttributeMaxDynamicSharedMemorySize, GEMM_SMEM);

    // weight transpose+split
    split_w<<<(512 * 1024 + 255) / 256, 256>>>(Wkv,   wkvh, wkvl, 512, 1024);
    split_w<<<(512 * 512  + 255) / 256, 256>>>(Wq,    wqh,  wql,  512, 512);
    split_w<<<(512 * 512  + 255) / 256, 256>>>(Wproj, wph,  wpl,  512, 512);

    // kv = x @ Wkv + bkv : [65536, 1024]
    gemm_mma<<<dim3(1024 / 128, (B_ * T_) / 128), 256, GEMM_SMEM>>>(
        x, wkvh, wkvl, bkv, kv, B_ * T_, 2 * D_, D_);
    // q = query @ Wq + bq : [2048, 512]
    gemm_mma<<<dim3(D_ / 128, (B_ * L_) / 128), 256, GEMM_SMEM>>>(
        query, wqh, wql, bq, q, B_ * L_, D_, D_);
    // attention -> att [2048, 512]
    attn_mma<<<B_ * H_ * (L_ / 128), 256>>>(q, kv, att);
    // out = att @ Wproj + bproj : [2048, 512]
    gemm_mma<<<dim3(D_ / 128, (B_ * L_) / 128), 256, GEMM_SMEM>>>(
        att, wph, wpl, bproj, out, B_ * L_, D_, D_);
}